// round 13
// baseline (speedup 1.0000x reference)
#include <cuda_runtime.h>
#include <cuda_bf16.h>
#include <cstdint>

#define D 256
#define BM 128
#define BNT 64               // T tile rows (n) per iteration
#define LDS_ROW 264          // 256 + 8 bf16 pad -> conflict-free ldmatrix
#define MAXN_PAD 100032      // multiple of 64, >= 100000
#define MAXB 1024
#define NSPLIT 38            // 8 qblocks * 38 = 304 CTAs = 2/SM on 152 SMs
#define NTHREADS 256

#define TILE_BYTES_G (BNT * D * 2)            // 32 KB contiguous per tile in gmem
#define BUF_BYTES    (BNT * LDS_ROW * 2)      // 33792 per smem buffer (padded rows)

__device__ __align__(256) __nv_bfloat16 g_tn[(size_t)MAXN_PAD * D];
__device__ __align__(256) __nv_bfloat16 g_qn[(size_t)MAXB * D];
__device__ float g_l[MAXB];
__device__ float g_s[MAXB];
__device__ unsigned int g_done;

// ---------------- tiny asm helpers ----------------

__device__ __forceinline__ void cp16(uint32_t dst, const void* src) {
    asm volatile("cp.async.cg.shared.global [%0], [%1], 16;" :: "r"(dst), "l"(src));
}
#define CP_COMMIT() asm volatile("cp.async.commit_group;" ::: "memory")
#define CP_WAIT1()  asm volatile("cp.async.wait_group 1;" ::: "memory")
#define CP_WAIT0()  asm volatile("cp.async.wait_group 0;" ::: "memory")

__device__ __forceinline__ float fsqrt_ap(float x) {
    float r; asm("sqrt.approx.f32 %0, %1;" : "=f"(r) : "f"(x)); return r;
}
__device__ __forceinline__ float fex2_ap(float x) {
    float r; asm("ex2.approx.f32 %0, %1;" : "=f"(r) : "f"(x)); return r;
}
#define LDSM4(r0, r1, r2, r3, addr) \
    asm volatile("ldmatrix.sync.aligned.m8n8.x4.shared.b16 {%0,%1,%2,%3}, [%4];" \
                 : "=r"(r0), "=r"(r1), "=r"(r2), "=r"(r3) : "r"(addr))
#define MMA16816(acc, a, b0, b1) \
    asm volatile("mma.sync.aligned.m16n8k16.row.col.f32.bf16.bf16.f32 " \
                 "{%0,%1,%2,%3}, {%4,%5,%6,%7}, {%8,%9}, {%0,%1,%2,%3};" \
                 : "+f"((acc)[0]), "+f"((acc)[1]), "+f"((acc)[2]), "+f"((acc)[3]) \
                 : "r"((a)[0]), "r"((a)[1]), "r"((a)[2]), "r"((a)[3]), \
                   "r"(b0), "r"(b1))

// ---------------- prep: L2-normalize fp32 -> bf16 (Q and T in one kernel) ----------------
// rows [0, Npad)        -> T
// rows [Npad, Npad + B) -> Q

__global__ void prep_kernel(const float* __restrict__ q, const float* __restrict__ t,
                            int B, int N, int Npad) {
    int gtid = blockIdx.x * blockDim.x + threadIdx.x;
    int row  = gtid >> 5;
    int lane = threadIdx.x & 31;
    if (gtid < MAXB) { g_l[gtid] = 0.f; g_s[gtid] = 0.f; }
    if (gtid == 0) g_done = 0u;
    if (row >= Npad + B) return;

    bool isQ = (row >= Npad);
    int  r   = isQ ? (row - Npad) : row;

    __nv_bfloat16* dst = (isQ ? g_qn : g_tn) + (size_t)r * D;

    if (!isQ && r >= N) {   // pad row: zeros
        *(uint4*)(dst + lane * 8) = make_uint4(0u, 0u, 0u, 0u);
        return;
    }

    const float4* src = (const float4*)((isQ ? q : t) + (size_t)r * D) + lane * 2;
    float4 v0 = src[0];
    float4 v1 = src[1];
    float ss = v0.x * v0.x + v0.y * v0.y + v0.z * v0.z + v0.w * v0.w
             + v1.x * v1.x + v1.y * v1.y + v1.z * v1.z + v1.w * v1.w;
#pragma unroll
    for (int o = 16; o > 0; o >>= 1) ss += __shfl_xor_sync(0xffffffffu, ss, o);
    float inv = 1.f / fmaxf(sqrtf(ss), 1e-12f);

    uint4 w;
    uint32_t* wp = (uint32_t*)&w;
    __nv_bfloat162 p0 = __floats2bfloat162_rn(v0.x * inv, v0.y * inv);
    __nv_bfloat162 p1 = __floats2bfloat162_rn(v0.z * inv, v0.w * inv);
    __nv_bfloat162 p2 = __floats2bfloat162_rn(v1.x * inv, v1.y * inv);
    __nv_bfloat162 p3 = __floats2bfloat162_rn(v1.z * inv, v1.w * inv);
    wp[0] = *(uint32_t*)&p0;
    wp[1] = *(uint32_t*)&p1;
    wp[2] = *(uint32_t*)&p2;
    wp[3] = *(uint32_t*)&p3;
    *(uint4*)(dst + lane * 8) = w;
}

// ---------------- main kernel ----------------
// 8 warps; warp tile 16 rows x 64 cols. A (Q bf16) in 64 registers.
// 3-stage cp.async T ring; Q staged through bufs 0+1 then overwritten.
// Loop nest: np outer, ks inner -> per-chunk epilogue interleaves with next
// chunk's MMAs, acc shrinks to 8 regs. 2 CTAs/SM; last CTA fuses finalize.

__global__ __launch_bounds__(NTHREADS, 2) void knn_main_kernel(
        float* __restrict__ out, int tilesTotal, int padCount) {
    extern __shared__ unsigned char smem_raw[];

    const int tid  = threadIdx.x;
    const int lane = tid & 31;
    const int warp = tid >> 5;
    const int wm   = warp;        // 0..7 -> 16-row slice of 128 query rows
    const int qb   = blockIdx.x;
    const int qbase = qb * BM;

    const int t0 = (int)(((long long)blockIdx.y       * tilesTotal) / gridDim.y);
    const int t1 = (int)(((long long)(blockIdx.y + 1) * tilesTotal) / gridDim.y);
    const int cnt = t1 - t0;

    const uint32_t smemB = (uint32_t)__cvta_generic_to_shared(smem_raw);
    const uint32_t bufA[3] = { smemB, smemB + BUF_BYTES, smemB + 2u * BUF_BYTES };

    // ---- stage Q [128 x 256] into bufs 0+1, hoist A to registers ----
    {
        const uint4* src = (const uint4*)(g_qn + (size_t)qbase * D);
        __nv_bfloat16* Qs = (__nv_bfloat16*)smem_raw;
#pragma unroll
        for (int i = 0; i < 16; i++) {
            int idx = tid + i * NTHREADS;         // 4096 chunks of 16B
            int r = idx >> 5, c8 = idx & 31;
            uint4 val = src[r * 32 + c8];
            *(uint4*)(Qs + r * LDS_ROW + c8 * 8) = val;
        }
    }
    __syncthreads();

    uint32_t Areg[16][4];
    {
        const int aRow  = lane & 15;
        const int aCoff = (lane >> 4) * 8;
        const uint32_t aBase = smemB +
            (uint32_t)(((wm * 16 + aRow) * LDS_ROW + aCoff) << 1);
#pragma unroll
        for (int ks = 0; ks < 16; ks++)
            LDSM4(Areg[ks][0], Areg[ks][1], Areg[ks][2], Areg[ks][3],
                  aBase + (uint32_t)(ks * 32));
    }
    __syncthreads();   // all hoists done before T copies overwrite staging

    // ---- prologue: tiles t0 -> buf0, t0+1 -> buf1 ----
#pragma unroll
    for (int p = 0; p < 2; p++) {
        if (p < cnt) {
            const char* src = (const char*)g_tn + (size_t)(t0 + p) * TILE_BYTES_G;
#pragma unroll
            for (int i = 0; i < 8; i++) {
                int idx = tid + i * NTHREADS;     // 2048 chunks of 16B
                int r = idx >> 5, c = idx & 31;
                cp16(bufA[p] + r * (LDS_ROW * 2) + c * 16, src + r * 512 + c * 16);
            }
            CP_COMMIT();
        }
    }

    float lrow[2] = {0.f, 0.f}, srow[2] = {0.f, 0.f};

    // B ldmatrix x4 addressing: 16 n-rows per load
    const int bR = (lane & 7) + ((lane >> 4) << 3);
    const int bC = ((lane >> 3) & 1) << 3;
    const uint32_t bThread = (uint32_t)((bR * LDS_ROW + bC) << 1);

    for (int i = 0; i < cnt; i++) {
        if (i + 1 < cnt) { CP_WAIT1(); } else { CP_WAIT0(); }
        __syncthreads();   // tile i visible; all warps done with buf (i-1)%3

        // prefetch tile i+2 into the just-released buffer
        if (i + 2 < cnt) {
            const char* src = (const char*)g_tn + (size_t)(t0 + i + 2) * TILE_BYTES_G;
            const uint32_t dstB = bufA[(i + 2) % 3];
#pragma unroll
            for (int u = 0; u < 8; u++) {
                int idx = tid + u * NTHREADS;
                int r = idx >> 5, c = idx & 31;
                cp16(dstB + r * (LDS_ROW * 2) + c * 16, src + r * 512 + c * 16);
            }
            CP_COMMIT();
        }

        const uint32_t TsB = bufA[i % 3] + bThread;

        // np outer / ks inner: per-chunk acc (8 regs), epilogue interleaved
#pragma unroll
        for (int np = 0; np < 4; np++) {
            const uint32_t npBase = TsB + (uint32_t)(np * 16 * LDS_ROW * 2);
            float acc0[4] = {0.f, 0.f, 0.f, 0.f};
            float acc1[4] = {0.f, 0.f, 0.f, 0.f};
#pragma unroll
            for (int ks = 0; ks < 16; ks++) {
                uint32_t b0, b1, b2, b3;
                LDSM4(b0, b1, b2, b3, npBase + (uint32_t)(ks * 32));
                MMA16816(acc0, Areg[ks], b0, b1);
                MMA16816(acc1, Areg[ks], b2, b3);
            }
            // epilogue for this 16-col chunk (8 elements) — overlaps next chunk's MMAs
#pragma unroll
            for (int j = 0; j < 4; j++) {
                float c  = acc0[j];
                float x  = fmaxf(fmaf(-2.f, c, 2.f), 0.f);
                float dd = fsqrt_ap(x);
                float e  = fex2_ap(dd * -14.4269504089f);   // exp(-10*d)
                int   h  = j >> 1;
                lrow[h] += e;
                srow[h]  = fmaf(e, dd, srow[h]);
            }
#pragma unroll
            for (int j = 0; j < 4; j++) {
                float c  = acc1[j];
                float x  = fmaxf(fmaf(-2.f, c, 2.f), 0.f);
                float dd = fsqrt_ap(x);
                float e  = fex2_ap(dd * -14.4269504089f);
                int   h  = j >> 1;
                lrow[h] += e;
                srow[h]  = fmaf(e, dd, srow[h]);
            }
        }
    }

    // lane-quad reduce; each query row owned by exactly one warp -> global atomics
#pragma unroll
    for (int h = 0; h < 2; h++) {
        float lv = lrow[h], sv = srow[h];
        lv += __shfl_xor_sync(0xffffffffu, lv, 1);
        lv += __shfl_xor_sync(0xffffffffu, lv, 2);
        sv += __shfl_xor_sync(0xffffffffu, sv, 1);
        sv += __shfl_xor_sync(0xffffffffu, sv, 2);
        if ((lane & 3) == 0) {
            int r = qbase + wm * 16 + (lane >> 2) + 8 * h;
            atomicAdd(&g_l[r], lv);
            atomicAdd(&g_s[r], sv);
        }
    }

    // last CTA computes the final output (no separate finalize launch)
    __shared__ unsigned int lastFlag;
    __threadfence();
    if (tid == 0)
        lastFlag = (atomicAdd(&g_done, 1u) == gridDim.x * gridDim.y - 1u) ? 1u : 0u;
    __syncthreads();
    if (lastFlag) {
        __threadfence();
        float d0 = fsqrt_ap(2.0f);
        float e0 = fex2_ap(d0 * -14.4269504089f);
        float fp = (float)padCount;
        int Btot = (int)gridDim.x * BM;
        for (int iq = tid; iq < Btot; iq += NTHREADS)
            out[iq] = (g_s[iq] - fp * e0 * d0) / (g_l[iq] - fp * e0);
    }
}

// ---------------- launch ----------------

extern "C" void kernel_launch(void* const* d_in, const int* in_sizes, int n_in,
                              void* d_out, int out_size) {
    const float* q = (const float*)d_in[0];
    const float* t = (const float*)d_in[1];
    int B = in_sizes[0] / D;
    int N = in_sizes[1] / D;
    if (B > MAXB) B = MAXB;
    int Npad = ((N + BNT - 1) / BNT) * BNT;
    if (Npad > MAXN_PAD) Npad = MAXN_PAD;
    int tilesTotal = Npad / BNT;
    int padCount = tilesTotal * BNT - N;

    const int smemBytes = 3 * BUF_BYTES;
    cudaFuncSetAttribute(knn_main_kernel,
                         cudaFuncAttributeMaxDynamicSharedMemorySize, smemBytes);

    prep_kernel<<<((Npad + B) * 32 + 255) / 256, 256>>>(q, t, B, N, Npad);

    int numQB = B / BM;
    if (numQB < 1) numQB = 1;
    knn_main_kernel<<<dim3(numQB, NSPLIT), NTHREADS, smemBytes>>>(
        (float*)d_out, tilesTotal, padCount);
}

// round 14
// speedup vs baseline: 1.2154x; 1.2154x over previous
#include <cuda_runtime.h>
#include <cuda_bf16.h>
#include <cstdint>

#define D 256
#define BM 128
#define BNT 64               // T tile rows (n) per iteration
#define LDS_ROW 264          // 256 + 8 bf16 pad -> conflict-free ldmatrix
#define MAXN_PAD 100032      // multiple of 64, >= 100000
#define MAXTILES (MAXN_PAD / BNT)   // 1563
#define MAXB 1024
#define NSPLIT 38            // 8 qblocks * 38 = 304 CTAs = 2/SM on 152 SMs
#define NTHREADS 256

#define TILE_BYTES_G (BNT * D * 2)            // 32 KB contiguous per tile in gmem
#define BUF_BYTES    (BNT * LDS_ROW * 2)      // 33792 per smem buffer (padded rows)

__device__ __align__(256) __nv_bfloat16 g_tn[(size_t)MAXN_PAD * D];
__device__ float g_l[MAXB];
__device__ float g_s[MAXB];
__device__ int   g_flags[MAXTILES];
__device__ unsigned int g_done;

// ---------------- tiny asm helpers ----------------

__device__ __forceinline__ void cp16(uint32_t dst, const void* src) {
    asm volatile("cp.async.cg.shared.global [%0], [%1], 16;" :: "r"(dst), "l"(src));
}
#define CP_COMMIT() asm volatile("cp.async.commit_group;" ::: "memory")
#define CP_WAIT1()  asm volatile("cp.async.wait_group 1;" ::: "memory")
#define CP_WAIT0()  asm volatile("cp.async.wait_group 0;" ::: "memory")

__device__ __forceinline__ float fsqrt_ap(float x) {
    float r; asm("sqrt.approx.f32 %0, %1;" : "=f"(r) : "f"(x)); return r;
}
__device__ __forceinline__ float fex2_ap(float x) {
    float r; asm("ex2.approx.f32 %0, %1;" : "=f"(r) : "f"(x)); return r;
}
#define LDSM4(r0, r1, r2, r3, addr) \
    asm volatile("ldmatrix.sync.aligned.m8n8.x4.shared.b16 {%0,%1,%2,%3}, [%4];" \
                 : "=r"(r0), "=r"(r1), "=r"(r2), "=r"(r3) : "r"(addr))
#define MMA16816(acc, a, b0, b1) \
    asm volatile("mma.sync.aligned.m16n8k16.row.col.f32.bf16.bf16.f32 " \
                 "{%0,%1,%2,%3}, {%4,%5,%6,%7}, {%8,%9}, {%0,%1,%2,%3};" \
                 : "+f"((acc)[0]), "+f"((acc)[1]), "+f"((acc)[2]), "+f"((acc)[3]) \
                 : "r"((a)[0]), "r"((a)[1]), "r"((a)[2]), "r"((a)[3]), \
                   "r"(b0), "r"(b1))

__device__ __forceinline__ void waitflag(int t) {
    while (atomicAdd(&g_flags[t], 0) == 0) { __nanosleep(64); }
}

// normalize one row of 256 fp32 (8 per lane) -> packed bf16 uint4 (warp-collective)
__device__ __forceinline__ uint4 norm_row(const float4* src2) {
    float4 v0 = src2[0];
    float4 v1 = src2[1];
    float ss = v0.x * v0.x + v0.y * v0.y + v0.z * v0.z + v0.w * v0.w
             + v1.x * v1.x + v1.y * v1.y + v1.z * v1.z + v1.w * v1.w;
#pragma unroll
    for (int o = 16; o > 0; o >>= 1) ss += __shfl_xor_sync(0xffffffffu, ss, o);
    float inv = 1.f / fmaxf(sqrtf(ss), 1e-12f);
    uint4 w;
    uint32_t* wp = (uint32_t*)&w;
    __nv_bfloat162 p0 = __floats2bfloat162_rn(v0.x * inv, v0.y * inv);
    __nv_bfloat162 p1 = __floats2bfloat162_rn(v0.z * inv, v0.w * inv);
    __nv_bfloat162 p2 = __floats2bfloat162_rn(v1.x * inv, v1.y * inv);
    __nv_bfloat162 p3 = __floats2bfloat162_rn(v1.z * inv, v1.w * inv);
    wp[0] = *(uint32_t*)&p0;
    wp[1] = *(uint32_t*)&p1;
    wp[2] = *(uint32_t*)&p2;
    wp[3] = *(uint32_t*)&p3;
    return w;
}

// ---------------- zero kernel: flags + accumulators ----------------

__global__ void zero_kernel() {
    int i = blockIdx.x * blockDim.x + threadIdx.x;
    if (i < MAXTILES) g_flags[i] = 0;
    if (i < MAXB) { g_l[i] = 0.f; g_s[i] = 0.f; }
    if (i == 0) g_done = 0u;
}

// ---------------- main kernel (fused prep + GEMM + softmax-sum + finalize) ----------------
// 8 warps; warp tile 16 rows x 64 cols. A (Q bf16) in 64 registers.
// In-kernel prep: Q normalized fp32->smem directly; T tiles normalized into
// g_tn by their owner CTA, published via flags. Mainloop identical to R10.

__global__ __launch_bounds__(NTHREADS, 2) void knn_main_kernel(
        float* __restrict__ out,
        const float* __restrict__ qin, const float* __restrict__ tin,
        int N, int tilesTotal, int padCount) {
    extern __shared__ unsigned char smem_raw[];

    const int tid  = threadIdx.x;
    const int lane = tid & 31;
    const int warp = tid >> 5;
    const int wm   = warp;        // 0..7 -> 16-row slice of 128 query rows
    const int qb   = blockIdx.x;
    const int qbase = qb * BM;
    const int gridQ = (int)gridDim.x;

    const int t0 = (int)(((long long)blockIdx.y       * tilesTotal) / gridDim.y);
    const int t1 = (int)(((long long)(blockIdx.y + 1) * tilesTotal) / gridDim.y);
    const int cnt = t1 - t0;

    const uint32_t smemB = (uint32_t)__cvta_generic_to_shared(smem_raw);
    const uint32_t bufA[3] = { smemB, smemB + BUF_BYTES, smemB + 2u * BUF_BYTES };

    // ---- 1) normalize this CTA's 128 Q rows fp32 -> bf16 staging (bufs 0+1) ----
#pragma unroll 4
    for (int rr = 0; rr < 16; rr++) {
        int row = wm * 16 + rr;
        const float4* src2 = (const float4*)(qin + (size_t)(qbase + row) * D) + lane * 2;
        uint4 w = norm_row(src2);
        *(uint4*)(smem_raw + row * (LDS_ROW * 2) + lane * 16) = w;
    }
    __syncthreads();

    // ---- 2) hoist A fragments ----
    uint32_t Areg[16][4];
    {
        const int aRow  = lane & 15;
        const int aCoff = (lane >> 4) * 8;
        const uint32_t aBase = smemB +
            (uint32_t)(((wm * 16 + aRow) * LDS_ROW + aCoff) << 1);
#pragma unroll
        for (int ks = 0; ks < 16; ks++)
            LDSM4(Areg[ks][0], Areg[ks][1], Areg[ks][2], Areg[ks][3],
                  aBase + (uint32_t)(ks * 32));
    }
    __syncthreads();   // staging dead; cp.async may overwrite later

    // ---- 3) prep my assigned T tiles: t in [t0,t1) with t % gridQ == qb ----
    const int first = t0 + (((qb - (t0 % gridQ)) % gridQ + gridQ) % gridQ);
    for (int t = first; t < t1; t += gridQ) {
#pragma unroll
        for (int rr = 0; rr < 8; rr++) {
            int grow = t * BNT + wm * 8 + rr;
            uint4 w;
            if (grow < N) {
                const float4* src2 = (const float4*)(tin + (size_t)grow * D) + lane * 2;
                w = norm_row(src2);
            } else {
                w = make_uint4(0u, 0u, 0u, 0u);
            }
            *(uint4*)((unsigned char*)g_tn + (size_t)grow * (D * 2) + lane * 16) = w;
        }
    }
    __threadfence();   // all my g_tn writes visible at gpu scope
    __syncthreads();
    {   // publish flags for my tiles (one thread per tile)
        int t = first + tid * gridQ;
        if (t < t1) atomicExch(&g_flags[t], 1);
    }

    // ---- 4) prologue: tiles t0 -> buf0, t0+1 -> buf1 (wait for producers) ----
#pragma unroll
    for (int p = 0; p < 2; p++) {
        if (p < cnt) {
            if (tid == 0) waitflag(t0 + p);
            __syncthreads();
            const char* src = (const char*)g_tn + (size_t)(t0 + p) * TILE_BYTES_G;
#pragma unroll
            for (int i = 0; i < 8; i++) {
                int idx = tid + i * NTHREADS;     // 2048 chunks of 16B
                int r = idx >> 5, c = idx & 31;
                cp16(bufA[p] + r * (LDS_ROW * 2) + c * 16, src + r * 512 + c * 16);
            }
            CP_COMMIT();
        }
    }

    float lrow[2] = {0.f, 0.f}, srow[2] = {0.f, 0.f};

    // B ldmatrix x4 addressing: 16 n-rows per load
    const int bR = (lane & 7) + ((lane >> 4) << 3);
    const int bC = ((lane >> 3) & 1) << 3;
    const uint32_t bThread = (uint32_t)((bR * LDS_ROW + bC) << 1);

    for (int i = 0; i < cnt; i++) {
        if (tid == 0 && i + 2 < cnt) waitflag(t0 + i + 2);
        if (i + 1 < cnt) { CP_WAIT1(); } else { CP_WAIT0(); }
        __syncthreads();   // tile i visible; all warps done with buf (i-1)%3; flag seen

        // prefetch tile i+2 into the just-released buffer
        if (i + 2 < cnt) {
            const char* src = (const char*)g_tn + (size_t)(t0 + i + 2) * TILE_BYTES_G;
            const uint32_t dstB = bufA[(i + 2) % 3];
#pragma unroll
            for (int u = 0; u < 8; u++) {
                int idx = tid + u * NTHREADS;
                int r = idx >> 5, c = idx & 31;
                cp16(dstB + r * (LDS_ROW * 2) + c * 16, src + r * 512 + c * 16);
            }
            CP_COMMIT();
        }

        const uint32_t TsB = bufA[i % 3] + bThread;

        float acc[8][4];
#pragma unroll
        for (int nt = 0; nt < 8; nt++)
#pragma unroll
            for (int j = 0; j < 4; j++) acc[nt][j] = 0.f;

#pragma unroll
        for (int ks = 0; ks < 16; ks++) {
            const uint32_t kOff = (uint32_t)(ks * 32);
#pragma unroll
            for (int np = 0; np < 4; np++) {    // 16 n-rows per ldmatrix x4
                uint32_t b0, b1, b2, b3;
                uint32_t addr = TsB + (uint32_t)(np * 16 * LDS_ROW * 2) + kOff;
                LDSM4(b0, b1, b2, b3, addr);
                MMA16816(acc[2 * np],     Areg[ks], b0, b1);
                MMA16816(acc[2 * np + 1], Areg[ks], b2, b3);
            }
        }

        // Fused epilogue — no masking (pad rows handled analytically below)
#pragma unroll
        for (int nt = 0; nt < 8; nt++)
#pragma unroll
            for (int j = 0; j < 4; j++) {
                float c  = acc[nt][j];
                float x  = fmaxf(fmaf(-2.f, c, 2.f), 0.f);
                float dd = fsqrt_ap(x);
                float e  = fex2_ap(dd * -14.4269504089f);   // exp(-10*d)
                int   h  = j >> 1;
                lrow[h] += e;
                srow[h]  = fmaf(e, dd, srow[h]);
            }
    }

    // lane-quad reduce; each query row owned by exactly one warp -> global atomics
#pragma unroll
    for (int h = 0; h < 2; h++) {
        float lv = lrow[h], sv = srow[h];
        lv += __shfl_xor_sync(0xffffffffu, lv, 1);
        lv += __shfl_xor_sync(0xffffffffu, lv, 2);
        sv += __shfl_xor_sync(0xffffffffu, sv, 1);
        sv += __shfl_xor_sync(0xffffffffu, sv, 2);
        if ((lane & 3) == 0) {
            int r = qbase + wm * 16 + (lane >> 2) + 8 * h;
            atomicAdd(&g_l[r], lv);
            atomicAdd(&g_s[r], sv);
        }
    }

    // last CTA computes the final output (no separate finalize launch)
    __shared__ unsigned int lastFlag;
    __threadfence();
    if (tid == 0)
        lastFlag = (atomicAdd(&g_done, 1u) == gridDim.x * gridDim.y - 1u) ? 1u : 0u;
    __syncthreads();
    if (lastFlag) {
        __threadfence();
        float d0 = fsqrt_ap(2.0f);
        float e0 = fex2_ap(d0 * -14.4269504089f);
        float fp = (float)padCount;
        int Btot = (int)gridDim.x * BM;
        for (int iq = tid; iq < Btot; iq += NTHREADS)
            out[iq] = (g_s[iq] - fp * e0 * d0) / (g_l[iq] - fp * e0);
    }
}

// ---------------- launch ----------------

extern "C" void kernel_launch(void* const* d_in, const int* in_sizes, int n_in,
                              void* d_out, int out_size) {
    const float* q = (const float*)d_in[0];
    const float* t = (const float*)d_in[1];
    int B = in_sizes[0] / D;
    int N = in_sizes[1] / D;
    if (B > MAXB) B = MAXB;
    int Npad = ((N + BNT - 1) / BNT) * BNT;
    if (Npad > MAXN_PAD) Npad = MAXN_PAD;
    int tilesTotal = Npad / BNT;
    int padCount = tilesTotal * BNT - N;

    const int smemBytes = 3 * BUF_BYTES;
    cudaFuncSetAttribute(knn_main_kernel,
                         cudaFuncAttributeMaxDynamicSharedMemorySize, smemBytes);

    zero_kernel<<<(MAXTILES + 255) / 256, 256>>>();

    int numQB = B / BM;
    if (numQB < 1) numQB = 1;
    knn_main_kernel<<<dim3(numQB, NSPLIT), NTHREADS, smemBytes>>>(
        (float*)d_out, q, t, N, tilesTotal, padCount);
}

// round 16
// speedup vs baseline: 1.5210x; 1.2514x over previous
#include <cuda_runtime.h>
#include <cuda_bf16.h>
#include <cstdint>

#define D 256
#define BM 128
#define BNT 64               // T tile rows (n) per iteration
#define LDS_ROW 264          // 256 + 8 bf16 pad -> conflict-free ldmatrix
#define MAXN_PAD 100032      // multiple of 64, >= 100000
#define MAXB 1024
#define NSPLIT 38            // 8 qblocks * 38 = 304 CTAs = 2/SM on 152 SMs
#define NTHREADS 256

#define TILE_BYTES_G (BNT * D * 2)            // 32 KB contiguous per tile in gmem
#define BUF_BYTES    (BNT * LDS_ROW * 2)      // 33792 per smem buffer (padded rows)
#define MBAR_OFF     (3 * BUF_BYTES)          // 6 mbarriers after the 3 buffers
#define SMEM_TOTAL   (MBAR_OFF + 64)

__device__ __align__(256) __nv_bfloat16 g_tn[(size_t)MAXN_PAD * D];
__device__ __align__(256) __nv_bfloat16 g_qn[(size_t)MAXB * D];
__device__ float g_l[MAXB];
__device__ float g_s[MAXB];
__device__ unsigned int g_done;

// ---------------- tiny asm helpers ----------------

__device__ __forceinline__ void cp16(uint32_t dst, const void* src) {
    asm volatile("cp.async.cg.shared.global [%0], [%1], 16;" :: "r"(dst), "l"(src));
}
#define CP_COMMIT() asm volatile("cp.async.commit_group;" ::: "memory")
#define CP_WAIT2()  asm volatile("cp.async.wait_group 2;" ::: "memory")
#define CP_WAIT1()  asm volatile("cp.async.wait_group 1;" ::: "memory")
#define CP_WAIT0()  asm volatile("cp.async.wait_group 0;" ::: "memory")

#define MBAR_INIT(addr, cnt) \
    asm volatile("mbarrier.init.shared.b64 [%0], %1;" :: "r"(addr), "r"(cnt) : "memory")
#define MBAR_ARRIVE(addr) \
    asm volatile("mbarrier.arrive.release.cta.shared::cta.b64 _, [%0];" :: "r"(addr) : "memory")

__device__ __forceinline__ void mbar_wait(uint32_t addr, uint32_t ph) {
    uint32_t done;
    do {
        asm volatile("{\n\t.reg .pred p;\n\t"
            "mbarrier.try_wait.parity.acquire.cta.shared::cta.b64 p, [%1], %2, 0x989680;\n\t"
            "selp.b32 %0, 1, 0, p;\n\t}"
            : "=r"(done) : "r"(addr), "r"(ph) : "memory");
    } while (!done);
}

__device__ __forceinline__ float fsqrt_ap(float x) {
    float r; asm("sqrt.approx.f32 %0, %1;" : "=f"(r) : "f"(x)); return r;
}
__device__ __forceinline__ float fex2_ap(float x) {
    float r; asm("ex2.approx.f32 %0, %1;" : "=f"(r) : "f"(x)); return r;
}
#define LDSM4(r0, r1, r2, r3, addr) \
    asm volatile("ldmatrix.sync.aligned.m8n8.x4.shared.b16 {%0,%1,%2,%3}, [%4];" \
                 : "=r"(r0), "=r"(r1), "=r"(r2), "=r"(r3) : "r"(addr))
#define MMA16816(acc, a, b0, b1) \
    asm volatile("mma.sync.aligned.m16n8k16.row.col.f32.bf16.bf16.f32 " \
                 "{%0,%1,%2,%3}, {%4,%5,%6,%7}, {%8,%9}, {%0,%1,%2,%3};" \
                 : "+f"((acc)[0]), "+f"((acc)[1]), "+f"((acc)[2]), "+f"((acc)[3]) \
                 : "r"((a)[0]), "r"((a)[1]), "r"((a)[2]), "r"((a)[3]), \
                   "r"(b0), "r"(b1))

// ---------------- prep: L2-normalize fp32 -> bf16 (Q and T in one kernel) ----------------

__global__ void prep_kernel(const float* __restrict__ q, const float* __restrict__ t,
                            int B, int N, int Npad) {
    int gtid = blockIdx.x * blockDim.x + threadIdx.x;
    int row  = gtid >> 5;
    int lane = threadIdx.x & 31;
    if (gtid < MAXB) { g_l[gtid] = 0.f; g_s[gtid] = 0.f; }
    if (gtid == 0) g_done = 0u;
    if (row >= Npad + B) return;

    bool isQ = (row >= Npad);
    int  r   = isQ ? (row - Npad) : row;

    __nv_bfloat16* dst = (isQ ? g_qn : g_tn) + (size_t)r * D;

    if (!isQ && r >= N) {   // pad row: zeros
        *(uint4*)(dst + lane * 8) = make_uint4(0u, 0u, 0u, 0u);
        return;
    }

    const float4* src = (const float4*)((isQ ? q : t) + (size_t)r * D) + lane * 2;
    float4 v0 = src[0];
    float4 v1 = src[1];
    float ss = v0.x * v0.x + v0.y * v0.y + v0.z * v0.z + v0.w * v0.w
             + v1.x * v1.x + v1.y * v1.y + v1.z * v1.z + v1.w * v1.w;
#pragma unroll
    for (int o = 16; o > 0; o >>= 1) ss += __shfl_xor_sync(0xffffffffu, ss, o);
    float inv = 1.f / fmaxf(sqrtf(ss), 1e-12f);

    uint4 w;
    uint32_t* wp = (uint32_t*)&w;
    __nv_bfloat162 p0 = __floats2bfloat162_rn(v0.x * inv, v0.y * inv);
    __nv_bfloat162 p1 = __floats2bfloat162_rn(v0.z * inv, v0.w * inv);
    __nv_bfloat162 p2 = __floats2bfloat162_rn(v1.x * inv, v1.y * inv);
    __nv_bfloat162 p3 = __floats2bfloat162_rn(v1.z * inv, v1.w * inv);
    wp[0] = *(uint32_t*)&p0;
    wp[1] = *(uint32_t*)&p1;
    wp[2] = *(uint32_t*)&p2;
    wp[3] = *(uint32_t*)&p3;
    *(uint4*)(dst + lane * 8) = w;
}

// ---------------- main kernel ----------------
// 8 warps; warp tile 16 rows x 64 cols. A (Q bf16) in 64 registers.
// 3-stage pipeline with NO per-tile __syncthreads:
//   producer completion: per-thread cp.async groups + arrive(full[s], count 256)
//   consumer release:    one arrive per warp on empty[s] (count 8)
// Warps flow independently -> one warp's MUFU epilogue overlaps others' HMMA.

__global__ __launch_bounds__(NTHREADS, 2) void knn_main_kernel(
        float* __restrict__ out, int tilesTotal, int padCount) {
    extern __shared__ unsigned char smem_raw[];

    const int tid  = threadIdx.x;
    const int lane = tid & 31;
    const int warp = tid >> 5;
    const int wm   = warp;        // 0..7 -> 16-row slice of 128 query rows
    const int qb   = blockIdx.x;
    const int qbase = qb * BM;

    const int t0 = (int)(((long long)blockIdx.y       * tilesTotal) / gridDim.y);
    const int t1 = (int)(((long long)(blockIdx.y + 1) * tilesTotal) / gridDim.y);
    const int cnt = t1 - t0;

    const uint32_t smemB = (uint32_t)__cvta_generic_to_shared(smem_raw);
    const uint32_t mb    = smemB + MBAR_OFF;   // full[s]=mb+8s, empty[s]=mb+24+8s

    if (tid == 0) {
#pragma unroll
        for (int s = 0; s < 3; s++) {
            MBAR_INIT(mb + s * 8, NTHREADS);       // full[s]: one arrive per thread
            MBAR_INIT(mb + 24 + s * 8, 8);         // empty[s]: one arrive per warp
        }
    }

    // ---- stage Q [128 x 256] into bufs 0+1, hoist A to registers ----
    {
        const uint4* src = (const uint4*)(g_qn + (size_t)qbase * D);
        __nv_bfloat16* Qs = (__nv_bfloat16*)smem_raw;
#pragma unroll
        for (int i = 0; i < 16; i++) {
            int idx = tid + i * NTHREADS;         // 4096 chunks of 16B
            int r = idx >> 5, c8 = idx & 31;
            uint4 val = src[r * 32 + c8];
            *(uint4*)(Qs + r * LDS_ROW + c8 * 8) = val;
        }
    }
    __syncthreads();   // Q staged + mbarriers initialized

    uint32_t Areg[16][4];
    {
        const int aRow  = lane & 15;
        const int aCoff = (lane >> 4) * 8;
        const uint32_t aBase = smemB +
            (uint32_t)(((wm * 16 + aRow) * LDS_ROW + aCoff) << 1);
#pragma unroll
        for (int ks = 0; ks < 16; ks++)
            LDSM4(Areg[ks][0], Areg[ks][1], Areg[ks][2], Areg[ks][3],
                  aBase + (uint32_t)(ks * 32));
    }
    __syncthreads();   // all hoists done before T copies overwrite staging

    uint32_t epM = 0x7u;   // empty-wait parity per stage, starts 1 (fresh pass)
    uint32_t fpM = 0x0u;   // full-wait parity per stage, starts 0

    // ---- prologue: produce tiles t0 -> stage0, t0+1 -> stage1 ----
#pragma unroll
    for (int p = 0; p < 2; p++) {
        if (p < cnt) {
            mbar_wait(mb + 24 + p * 8, (epM >> p) & 1u);
            epM ^= (1u << p);
            const char* src = (const char*)g_tn + (size_t)(t0 + p) * TILE_BYTES_G;
            const uint32_t dstB = smemB + (uint32_t)(p * BUF_BYTES);
#pragma unroll
            for (int i = 0; i < 8; i++) {
                int idx = tid + i * NTHREADS;     // 2048 chunks of 16B
                int r = idx >> 5, c = idx & 31;
                cp16(dstB + r * (LDS_ROW * 2) + c * 16, src + r * 512 + c * 16);
            }
            CP_COMMIT();
        }
    }

    float lrow[2] = {0.f, 0.f}, srow[2] = {0.f, 0.f};

    // B ldmatrix x4 addressing: 16 n-rows per load
    const int bR = (lane & 7) + ((lane >> 4) << 3);
    const int bC = ((lane >> 3) & 1) << 3;
    const uint32_t bThread = (uint32_t)((bR * LDS_ROW + bC) << 1);

    for (int i = 0; i < cnt; i++) {
        const int s = i % 3;

        // produce tile i+2 into stage (i+2)%3 (gated on all warps done with tile i-1)
        if (i + 2 < cnt) {
            const int s2 = (i + 2) % 3;
            mbar_wait(mb + 24 + s2 * 8, (epM >> s2) & 1u);
            epM ^= (1u << s2);
            const char* src = (const char*)g_tn + (size_t)(t0 + i + 2) * TILE_BYTES_G;
            const uint32_t dstB = smemB + (uint32_t)(s2 * BUF_BYTES);
#pragma unroll
            for (int u = 0; u < 8; u++) {
                int idx = tid + u * NTHREADS;
                int r = idx >> 5, c = idx & 31;
                cp16(dstB + r * (LDS_ROW * 2) + c * 16, src + r * 512 + c * 16);
            }
            CP_COMMIT();
        }

        // consume tile i: own copies done -> arrive(full) -> wait all 256 arrivals
        if (i + 2 < cnt)      { CP_WAIT2(); }
        else if (i + 1 < cnt) { CP_WAIT1(); }
        else                  { CP_WAIT0(); }
        MBAR_ARRIVE(mb + s * 8);
        mbar_wait(mb + s * 8, (fpM >> s) & 1u);
        fpM ^= (1u << s);

        const uint32_t TsB = smemB + (uint32_t)(s * BUF_BYTES) + bThread;

        float acc[8][4];
#pragma unroll
        for (int nt = 0; nt < 8; nt++)
#pragma unroll
            for (int j = 0; j < 4; j++) acc[nt][j] = 0.f;

#pragma unroll
        for (int ks = 0; ks < 16; ks++) {
            const uint32_t kOff = (uint32_t)(ks * 32);
#pragma unroll
            for (int np = 0; np < 4; np++) {    // 16 n-rows per ldmatrix x4
                uint32_t b0, b1, b2, b3;
                uint32_t addr = TsB + (uint32_t)(np * 16 * LDS_ROW * 2) + kOff;
                LDSM4(b0, b1, b2, b3, addr);
                MMA16816(acc[2 * np],     Areg[ks], b0, b1);
                MMA16816(acc[2 * np + 1], Areg[ks], b2, b3);
            }
        }

        // Fused epilogue — no masking (pad rows handled analytically below)
#pragma unroll
        for (int nt = 0; nt < 8; nt++)
#pragma unroll
            for (int j = 0; j < 4; j++) {
                float c  = acc[nt][j];
                float x  = fmaxf(fmaf(-2.f, c, 2.f), 0.f);
                float dd = fsqrt_ap(x);
                float e  = fex2_ap(dd * -14.4269504089f);   // exp(-10*d)
                int   h  = j >> 1;
                lrow[h] += e;
                srow[h]  = fmaf(e, dd, srow[h]);
            }

        __syncwarp();
        if (lane == 0) MBAR_ARRIVE(mb + 24 + s * 8);   // this warp releases stage s
    }

    // lane-quad reduce; each query row owned by exactly one warp -> global atomics
#pragma unroll
    for (int h = 0; h < 2; h++) {
        float lv = lrow[h], sv = srow[h];
        lv += __shfl_xor_sync(0xffffffffu, lv, 1);
        lv += __shfl_xor_sync(0xffffffffu, lv, 2);
        sv += __shfl_xor_sync(0xffffffffu, sv, 1);
        sv += __shfl_xor_sync(0xffffffffu, sv, 2);
        if ((lane & 3) == 0) {
            int r = qbase + wm * 16 + (lane >> 2) + 8 * h;
            atomicAdd(&g_l[r], lv);
            atomicAdd(&g_s[r], sv);
        }
    }

    // last CTA computes the final output (no separate finalize launch)
    __shared__ unsigned int lastFlag;
    __threadfence();
    __syncthreads();
    if (tid == 0)
        lastFlag = (atomicAdd(&g_done, 1u) == gridDim.x * gridDim.y - 1u) ? 1u : 0u;
    __syncthreads();
    if (lastFlag) {
        __threadfence();
        float d0 = fsqrt_ap(2.0f);
        float e0 = fex2_ap(d0 * -14.4269504089f);
        float fp = (float)padCount;
        int Btot = (int)gridDim.x * BM;
        for (int iq = tid; iq < Btot; iq += NTHREADS)
            out[iq] = (g_s[iq] - fp * e0 * d0) / (g_l[iq] - fp * e0);
    }
}

// ---------------- launch ----------------

extern "C" void kernel_launch(void* const* d_in, const int* in_sizes, int n_in,
                              void* d_out, int out_size) {
    const float* q = (const float*)d_in[0];
    const float* t = (const float*)d_in[1];
    int B = in_sizes[0] / D;
    int N = in_sizes[1] / D;
    if (B > MAXB) B = MAXB;
    int Npad = ((N + BNT - 1) / BNT) * BNT;
    if (Npad > MAXN_PAD) Npad = MAXN_PAD;
    int tilesTotal = Npad / BNT;
    int padCount = tilesTotal * BNT - N;

    cudaFuncSetAttribute(knn_main_kernel,
                         cudaFuncAttributeMaxDynamicSharedMemorySize, SMEM_TOTAL);

    prep_kernel<<<((Npad + B) * 32 + 255) / 256, 256>>>(q, t, B, N, Npad);

    int numQB = B / BM;
    if (numQB < 1) numQB = 1;
    knn_main_kernel<<<dim3(numQB, NSPLIT), NTHREADS, SMEM_TOTAL>>>(
        (float*)d_out, tilesTotal, padCount);
}